// round 3
// baseline (speedup 1.0000x reference)
#include <cuda_runtime.h>
#include <cuda_bf16.h>
#include <cstdint>

#define NUM_CLASSES 1000
#define EMBED_DIM   1024
#define BATCH       32768
#define FACTOR      0.3f

// Scratch (no device allocation allowed -> __device__ globals)
__device__ float g_counts[NUM_CLASSES];
__device__ int   g_y_is_i32;

// ---------------------------------------------------------------------------
// Kernel 1: dtype probe for y + zero g_counts.
// If y is int64 (little-endian) with values in [0,1000), every odd 32-bit
// word in the first 32768 words is 0. If y is int32, those words are random
// class ids (P(all zero) ~ 1000^-16384 ~ 0). Only touches the first 32768
// 32-bit words, which is in-bounds for BOTH dtypes.
// ---------------------------------------------------------------------------
__global__ void probe_and_zero_kernel(const unsigned int* __restrict__ yw) {
    __shared__ int found;
    if (threadIdx.x == 0) found = 0;
    __syncthreads();

    // zero counts
    for (int i = threadIdx.x; i < NUM_CLASSES; i += blockDim.x)
        g_counts[i] = 0.0f;

    // scan odd words among the first 32768 32-bit words
    int nonzero = 0;
    for (int i = threadIdx.x; i < BATCH / 2; i += blockDim.x) {
        if (yw[2 * i + 1] != 0u) { nonzero = 1; break; }
    }
    if (nonzero) found = 1;
    __syncthreads();
    if (threadIdx.x == 0) g_y_is_i32 = found;
}

// ---------------------------------------------------------------------------
// Kernel 2: scatter-add. One block per row, one float4 per thread.
// Vector reduction (red.global.add.v4.f32) quarters the LTS atomic op count.
// d_out doubles as the per-class sum accumulator (pre-zeroed by memset).
// ---------------------------------------------------------------------------
__global__ void __launch_bounds__(256)
scatter_kernel(const float4* __restrict__ embed,
               const void*   __restrict__ y,
               float4*       __restrict__ sums) {
    const int row = blockIdx.x;
    int cls;
    if (g_y_is_i32)
        cls = ((const int*)y)[row];
    else
        cls = (int)(((const long long*)y)[row]);

    const int t = threadIdx.x;                 // 0..255 float4 chunks of D=1024
    float4 v = embed[(size_t)row * (EMBED_DIM / 4) + t];
    float4* dst = sums + (size_t)cls * (EMBED_DIM / 4) + t;

    asm volatile("red.global.add.v4.f32 [%0], {%1, %2, %3, %4};"
                 :: "l"(dst), "f"(v.x), "f"(v.y), "f"(v.z), "f"(v.w)
                 : "memory");

    if (t == 0)
        atomicAdd(&g_counts[cls], 1.0f);
}

// ---------------------------------------------------------------------------
// Kernel 3: finalize in place. out = FACTOR * sums/count + (1-FACTOR)*centroid
// float4-vectorized: 1000*1024/4 = 256000 elements.
// ---------------------------------------------------------------------------
__global__ void __launch_bounds__(256)
finalize_kernel(const float4* __restrict__ centroid,
                float4*       __restrict__ out) {
    const int i = blockIdx.x * blockDim.x + threadIdx.x;   // < 256000
    const int c = i >> 8;                                  // 256 float4 per row
    const float inv = FACTOR / g_counts[c];

    float4 s  = out[i];
    float4 ce = centroid[i];
    float4 r;
    r.x = s.x * inv + (1.0f - FACTOR) * ce.x;
    r.y = s.y * inv + (1.0f - FACTOR) * ce.y;
    r.z = s.z * inv + (1.0f - FACTOR) * ce.z;
    r.w = s.w * inv + (1.0f - FACTOR) * ce.w;
    out[i] = r;
}

// ---------------------------------------------------------------------------
extern "C" void kernel_launch(void* const* d_in, const int* in_sizes, int n_in,
                              void* d_out, int out_size) {
    const float4*       embed    = (const float4*)d_in[0];
    const void*         y        = d_in[1];
    const float4*       centroid = (const float4*)d_in[2];
    float4*             out      = (float4*)d_out;

    // 1) probe y dtype + zero counts
    probe_and_zero_kernel<<<1, 1024>>>((const unsigned int*)y);

    // 2) zero the accumulator (d_out doubles as sums buffer)
    cudaMemsetAsync(d_out, 0, (size_t)NUM_CLASSES * EMBED_DIM * sizeof(float));

    // 3) scatter-add rows into per-class sums
    scatter_kernel<<<BATCH, 256>>>(embed, y, out);

    // 4) finalize: mean, blend with old centroid
    finalize_kernel<<<(NUM_CLASSES * EMBED_DIM / 4) / 256, 256>>>(centroid, out);
}